// round 2
// baseline (speedup 1.0000x reference)
#include <cuda_runtime.h>
#include <math.h>

#define NN 8192
#define WD 64
#define OUTD 256
#define IFACED 471
#define CD 727
#define FCD 2908
#define KS 16
#define KCH 46
#define KS2 8
#define KCH2 91

__device__ __align__(16) float g_seq[5 * WD];
__device__ float g_h[CD], g_c[CD];
__device__ float g_zpart[KS * FCD];
__device__ float g_oppart[KS2 * CD];
__device__ float g_outv[OUTD];
__device__ float g_kwn[WD];
__device__ float g_krn[4 * WD];
__device__ float g_bread[4], g_bwrite;
__device__ float g_erase[WD], g_writev[WD];
__device__ float g_free[4], g_ag, g_wg;
__device__ float g_rm[12];
__device__ float g_usage[NN];
__device__ float g_Walloc[NN];
__device__ float g_ew[NN];
__device__ float g_sumw;
__device__ __align__(16) float g_Ww[NN];
__device__ __align__(16) float g_M[NN * WD];
__device__ __align__(16) float g_Wfwd[NN * 4];
__device__ __align__(16) float g_Wbwd[NN * 4];
__device__ __align__(16) float g_er[NN * 4];
__device__ float g_sumr[4];
__device__ float g_rv[OUTD];

__device__ __forceinline__ float sigm(float x) { return 1.f / (1.f + expf(-x)); }
__device__ __forceinline__ float sp(float x) { return x > 20.f ? x : log1pf(expf(x)); }

__global__ void k_prep(const float* __restrict__ x, const float* __restrict__ dk,
                       const float* __restrict__ db, const float* __restrict__ h,
                       const float* __restrict__ c, const float* __restrict__ read_v) {
    int t = threadIdx.x;
    if (t < WD) {
        float acc = db[t];
#pragma unroll 8
        for (int k = 0; k < 256; k++) acc += x[k] * dk[k * WD + t];
        g_seq[t] = acc;
    }
    if (t < 256) g_seq[WD + t] = read_v[t];
    if (t < CD) { g_h[t] = h[t]; g_c[t] = c[t]; }
}

__global__ void k_lstmA(const float* __restrict__ lstm_k, const float* __restrict__ lstm_r,
                        const float* __restrict__ lstm_b, int t) {
    __shared__ float s_h[KCH];
    const int j = blockIdx.x * 256 + threadIdx.x;
    const int kc = blockIdx.y;
    const int k0 = kc * KCH;
    const int kn = min(KCH, CD - k0);
    for (int k = threadIdx.x; k < kn; k += 256) s_h[k] = g_h[k0 + k];
    __syncthreads();
    if (j >= FCD) return;
    float acc = 0.f;
    if (kc == 0) {
        acc = lstm_b[j];
        const float* xt = g_seq + t * WD;
#pragma unroll 8
        for (int k = 0; k < WD; k++) acc += xt[k] * lstm_k[k * FCD + j];
    }
#pragma unroll 4
    for (int k = 0; k < kn; k++) acc += s_h[k] * lstm_r[(size_t)(k0 + k) * FCD + j];
    g_zpart[kc * FCD + j] = acc;
}

__global__ void k_lstmB() {
    const int j = blockIdx.x * 256 + threadIdx.x;
    if (j >= CD) return;
    float zi = 0.f, zf = 0.f, zg = 0.f, zo = 0.f;
#pragma unroll
    for (int p = 0; p < KS; p++) {
        const float* zp = g_zpart + p * FCD;
        zi += zp[j]; zf += zp[CD + j]; zg += zp[2 * CD + j]; zo += zp[3 * CD + j];
    }
    float cn = sigm(zf) * g_c[j] + sigm(zi) * tanhf(zg);
    g_c[j] = cn;
    g_h[j] = sigm(zo) * tanhf(cn);
}

__global__ void k_proj(const float* __restrict__ Wout, const float* __restrict__ Wif) {
    __shared__ float sh[KCH2];
    const int j = blockIdx.x * 256 + threadIdx.x;
    const int kc = blockIdx.y;
    const int k0 = kc * KCH2;
    const int kn = min(KCH2, CD - k0);
    for (int k = threadIdx.x; k < kn; k += 256) sh[k] = g_h[k0 + k];
    __syncthreads();
    if (j >= CD) return;
    float acc = 0.f;
    if (j < 256) {
#pragma unroll 4
        for (int k = 0; k < kn; k++) acc += sh[k] * Wout[(size_t)(k0 + k) * 256 + j];
    } else {
        int jj = j - 256;
#pragma unroll 4
        for (int k = 0; k < kn; k++) acc += sh[k] * Wif[(size_t)(k0 + k) * IFACED + jj];
    }
    g_oppart[kc * CD + j] = acc;
}

__global__ void k_parse() {
    __shared__ float sif[IFACED];
    const int t = threadIdx.x;
    if (t < CD) {
        float v = 0.f;
#pragma unroll
        for (int p = 0; p < KS2; p++) v += g_oppart[p * CD + t];
        if (t < 256) g_outv[t] = v; else sif[t - 256] = v;
    }
    __syncthreads();
    const int w = t >> 5, lane = t & 31;
    if (w == 0) {  // k_write at iface[260:324]
        float s = 0.f;
        for (int e = lane; e < 64; e += 32) { float v = sif[260 + e]; s += v * v; }
        for (int o = 16; o; o >>= 1) s += __shfl_xor_sync(0xffffffffu, s, o);
        float inv = rsqrtf(fmaxf(s, 1e-12f));
        for (int e = lane; e < 64; e += 32) g_kwn[e] = sif[260 + e] * inv;
    } else if (w <= 4) {  // k_read rows at iface[0:256]
        int r = w - 1;
        float s = 0.f;
        for (int e = lane; e < 64; e += 32) { float v = sif[r * 64 + e]; s += v * v; }
        for (int o = 16; o; o >>= 1) s += __shfl_xor_sync(0xffffffffu, s, o);
        float inv = rsqrtf(fmaxf(s, 1e-12f));
        for (int e = lane; e < 64; e += 32) g_krn[r * 64 + e] = sif[r * 64 + e] * inv;
    } else if (w == 5) {
        if (lane < 4) g_bread[lane] = 1.f + sp(sif[256 + lane]);
        if (lane == 4) g_bwrite = 1.f + sp(sif[324]);
        if (lane >= 8 && lane < 12) g_free[lane - 8] = sigm(sif[453 + lane - 8]);
        if (lane == 12) g_ag = sigm(sif[457]);
        if (lane == 13) g_wg = sigm(sif[458]);
        if (lane >= 16 && lane < 20) {  // read modes: softmax over 3, layout (3,4)
            int r = lane - 16;
            float e0 = expf(sif[459 + r]);
            float e1 = expf(sif[463 + r]);
            float e2 = expf(sif[467 + r]);
            float si = 1.f / (e0 + e1 + e2);
            g_rm[r] = e0 * si; g_rm[4 + r] = e1 * si; g_rm[8 + r] = e2 * si;
        }
    } else if (w == 6) {
        for (int e = lane; e < 64; e += 32) {
            g_erase[e] = sigm(sif[325 + e]);
            g_writev[e] = sif[389 + e];
        }
    }
}

__global__ void k_usage(const float* __restrict__ usage_in, const float* __restrict__ Wread_in,
                        const float* __restrict__ Wwrite_in) {
    const int i = blockIdx.x * 256 + threadIdx.x;
    if (i >= NN) return;
    float ret = 1.f;
#pragma unroll
    for (int r = 0; r < 4; r++) ret *= (1.f - g_free[r] * Wread_in[i * 4 + r]);
    float u = usage_in[i], ww = Wwrite_in[i];
    g_usage[i] = (u + ww - u * ww) * ret;
    float4 z = make_float4(0.f, 0.f, 0.f, 0.f);
    ((float4*)g_Wfwd)[i] = z;
    ((float4*)g_Wbwd)[i] = z;
    if (i < OUTD) g_rv[i] = 0.f;
    if (i == 0) g_sumw = 0.f;
    if (i < 4) g_sumr[i] = 0.f;
}

// stable ascending argsort (bitonic on (usage_bits, idx)) + exclusive cumprod -> W_alloc
__global__ void k_sort() {
    extern __shared__ unsigned long long key[];
    __shared__ float wtot[32];
    const int t = threadIdx.x;
    for (int i = t; i < NN; i += 1024) {
        unsigned ub = __float_as_uint(g_usage[i]);  // usage >= 0
        key[i] = ((unsigned long long)ub << 32) | (unsigned)i;
    }
    __syncthreads();
    for (int k = 2; k <= NN; k <<= 1)
        for (int j = k >> 1; j > 0; j >>= 1) {
            for (int i = t; i < NN; i += 1024) {
                int ixj = i ^ j;
                if (ixj > i) {
                    unsigned long long a = key[i], b = key[ixj];
                    bool up = ((i & k) == 0);
                    if ((a > b) == up) { key[i] = b; key[ixj] = a; }
                }
            }
            __syncthreads();
        }
    float loc[8], p = 1.f;
#pragma unroll
    for (int m = 0; m < 8; m++) {
        loc[m] = p;
        p *= __uint_as_float((unsigned)(key[t * 8 + m] >> 32));
    }
    const int lane = t & 31, w = t >> 5;
    float sc = p;
    for (int o = 1; o < 32; o <<= 1) {
        float v = __shfl_up_sync(0xffffffffu, sc, o);
        if (lane >= o) sc *= v;
    }
    if (lane == 31) wtot[w] = sc;
    __syncthreads();
    if (w == 0) {
        float s2 = wtot[lane];
        for (int o = 1; o < 32; o <<= 1) {
            float z = __shfl_up_sync(0xffffffffu, s2, o);
            if (lane >= o) s2 *= z;
        }
        wtot[lane] = s2;
    }
    __syncthreads();
    float excl = __shfl_up_sync(0xffffffffu, sc, 1);
    if (lane == 0) excl = 1.f;
    float pref = (w > 0 ? wtot[w - 1] : 1.f) * excl;
#pragma unroll
    for (int m = 0; m < 8; m++) {
        unsigned long long kk = key[t * 8 + m];
        float u = __uint_as_float((unsigned)(kk >> 32));
        int idx = (int)(unsigned)(kk & 0xffffffffu);
        g_Walloc[idx] = (1.f - u) * pref * loc[m];
    }
}

__global__ void k_wscore(const float* __restrict__ M) {
    __shared__ float bsum[8];
    const int w = threadIdx.x >> 5, lane = threadIdx.x & 31;
    const int wg = blockIdx.x * 8 + w;
    const float ka = g_kwn[lane], kb = g_kwn[lane + 32];
    const float bw = g_bwrite;
    float local = 0.f;
    for (int rr = 0; rr < 16; rr++) {
        int i = wg * 16 + rr;
        const float* row = M + (size_t)i * WD;
        float a0 = row[lane], a1 = row[lane + 32];
        float ss = a0 * a0 + a1 * a1;
        float d = a0 * ka + a1 * kb;
        for (int o = 16; o; o >>= 1) {
            ss += __shfl_xor_sync(0xffffffffu, ss, o);
            d += __shfl_xor_sync(0xffffffffu, d, o);
        }
        if (lane == 0) {
            float e = expf(bw * d * rsqrtf(fmaxf(ss, 1e-12f)));
            g_ew[i] = e;
            local += e;
        }
    }
    if (lane == 0) bsum[w] = local;
    __syncthreads();
    if (threadIdx.x == 0) {
        float s = 0.f;
        for (int k = 0; k < 8; k++) s += bsum[k];
        atomicAdd(&g_sumw, s);
    }
}

__global__ void k_writeM(const float* __restrict__ M) {
    const float inv_s = 1.f / g_sumw;
    const float wgt = g_wg, ag = g_ag, iag = 1.f - g_ag;
    for (int e = blockIdx.x * blockDim.x + threadIdx.x; e < NN * WD; e += gridDim.x * blockDim.x) {
        int i = e >> 6, wc = e & 63;
        float ww = wgt * (ag * g_Walloc[i] + iag * g_ew[i] * inv_s);
        g_M[e] = M[e] * (1.f - ww * g_erase[wc]) + ww * g_writev[wc];
        if (wc == 0) g_Ww[i] = ww;
    }
}

// fused: W_fwd = L_new @ Wr, W_bwd = L_new^T @ Wr with L_new formed on the fly
__global__ void __launch_bounds__(256) k_link(const float* __restrict__ L,
                                              const float* __restrict__ Wprec,
                                              const float* __restrict__ Wread) {
    __shared__ float s_ww[1024];
    __shared__ float s_wr[1024 * 4];
    const int jb = blockIdx.x, ib = blockIdx.y;
    const int i0 = ib * 1024;
    for (int k = threadIdx.x; k < 1024; k += 256) {
        s_ww[k] = g_Ww[i0 + k];
        float4 v = ((const float4*)Wread)[i0 + k];
        s_wr[k * 4] = v.x; s_wr[k * 4 + 1] = v.y; s_wr[k * 4 + 2] = v.z; s_wr[k * 4 + 3] = v.w;
    }
    __syncthreads();
    const int w = threadIdx.x >> 5, lane = threadIdx.x & 31;
    const int j0 = jb * 256 + lane * 4;
    float tj[2][4], wpj[2][4], wrj[2][4][4], bwd[2][4][4];
#pragma unroll
    for (int cc = 0; cc < 2; cc++) {
        int jj = j0 + cc * 128;
        float4 a = *(const float4*)(g_Ww + jj);
        tj[cc][0] = 1.f - a.x; tj[cc][1] = 1.f - a.y; tj[cc][2] = 1.f - a.z; tj[cc][3] = 1.f - a.w;
        float4 b = *(const float4*)(Wprec + jj);
        wpj[cc][0] = b.x; wpj[cc][1] = b.y; wpj[cc][2] = b.z; wpj[cc][3] = b.w;
#pragma unroll
        for (int k2 = 0; k2 < 4; k2++) {
            float4 v = ((const float4*)Wread)[jj + k2];
            wrj[cc][k2][0] = v.x; wrj[cc][k2][1] = v.y; wrj[cc][k2][2] = v.z; wrj[cc][k2][3] = v.w;
            bwd[cc][k2][0] = bwd[cc][k2][1] = bwd[cc][k2][2] = bwd[cc][k2][3] = 0.f;
        }
    }
    for (int il = w; il < 1024; il += 8) {
        const int i = i0 + il;
        const float4* Lr = (const float4*)(L + (size_t)i * NN);
        const float wwi = s_ww[il];
        const float wri0 = s_wr[il * 4], wri1 = s_wr[il * 4 + 1];
        const float wri2 = s_wr[il * 4 + 2], wri3 = s_wr[il * 4 + 3];
        float f0 = 0.f, f1 = 0.f, f2 = 0.f, f3 = 0.f;
#pragma unroll
        for (int cc = 0; cc < 2; cc++) {
            float4 lv = Lr[(j0 >> 2) + cc * 32];
            float le[4] = {lv.x, lv.y, lv.z, lv.w};
#pragma unroll
            for (int k2 = 0; k2 < 4; k2++) {
                float nl = (tj[cc][k2] - wwi) * le[k2] + wwi * wpj[cc][k2];
                if (j0 + cc * 128 + k2 == i) nl = 0.f;
                f0 += nl * wrj[cc][k2][0];
                f1 += nl * wrj[cc][k2][1];
                f2 += nl * wrj[cc][k2][2];
                f3 += nl * wrj[cc][k2][3];
                bwd[cc][k2][0] += nl * wri0;
                bwd[cc][k2][1] += nl * wri1;
                bwd[cc][k2][2] += nl * wri2;
                bwd[cc][k2][3] += nl * wri3;
            }
        }
#pragma unroll
        for (int o = 16; o; o >>= 1) {
            f0 += __shfl_xor_sync(0xffffffffu, f0, o);
            f1 += __shfl_xor_sync(0xffffffffu, f1, o);
            f2 += __shfl_xor_sync(0xffffffffu, f2, o);
            f3 += __shfl_xor_sync(0xffffffffu, f3, o);
        }
        float fv = lane == 0 ? f0 : lane == 1 ? f1 : lane == 2 ? f2 : f3;
        if (lane < 4) atomicAdd(&g_Wfwd[i * 4 + lane], fv);
    }
#pragma unroll
    for (int cc = 0; cc < 2; cc++)
#pragma unroll
        for (int k2 = 0; k2 < 4; k2++)
#pragma unroll
            for (int r = 0; r < 4; r++)
                atomicAdd(&g_Wbwd[(j0 + cc * 128 + k2) * 4 + r], bwd[cc][k2][r]);
}

__global__ void k_rscore() {
    __shared__ float bs[8][4];
    const int w = threadIdx.x >> 5, lane = threadIdx.x & 31;
    const int wg = blockIdx.x * 8 + w;
    const float k0a = g_krn[lane], k0b = g_krn[lane + 32];
    const float k1a = g_krn[64 + lane], k1b = g_krn[96 + lane];
    const float k2a = g_krn[128 + lane], k2b = g_krn[160 + lane];
    const float k3a = g_krn[192 + lane], k3b = g_krn[224 + lane];
    const float br0 = g_bread[0], br1 = g_bread[1], br2 = g_bread[2], br3 = g_bread[3];
    float l0 = 0.f, l1 = 0.f, l2 = 0.f, l3 = 0.f;
    for (int rr = 0; rr < 16; rr++) {
        int i = wg * 16 + rr;
        const float* row = g_M + (size_t)i * WD;
        float a0 = row[lane], a1 = row[lane + 32];
        float ss = a0 * a0 + a1 * a1;
        float d0 = a0 * k0a + a1 * k0b;
        float d1 = a0 * k1a + a1 * k1b;
        float d2 = a0 * k2a + a1 * k2b;
        float d3 = a0 * k3a + a1 * k3b;
        for (int o = 16; o; o >>= 1) {
            ss += __shfl_xor_sync(0xffffffffu, ss, o);
            d0 += __shfl_xor_sync(0xffffffffu, d0, o);
            d1 += __shfl_xor_sync(0xffffffffu, d1, o);
            d2 += __shfl_xor_sync(0xffffffffu, d2, o);
            d3 += __shfl_xor_sync(0xffffffffu, d3, o);
        }
        if (lane == 0) {
            float inv = rsqrtf(fmaxf(ss, 1e-12f));
            float e0 = expf(br0 * d0 * inv), e1 = expf(br1 * d1 * inv);
            float e2 = expf(br2 * d2 * inv), e3 = expf(br3 * d3 * inv);
            g_er[i * 4] = e0; g_er[i * 4 + 1] = e1; g_er[i * 4 + 2] = e2; g_er[i * 4 + 3] = e3;
            l0 += e0; l1 += e1; l2 += e2; l3 += e3;
        }
    }
    if (lane == 0) { bs[w][0] = l0; bs[w][1] = l1; bs[w][2] = l2; bs[w][3] = l3; }
    __syncthreads();
    if (threadIdx.x < 4) {
        float s = 0.f;
        for (int k = 0; k < 8; k++) s += bs[k][threadIdx.x];
        atomicAdd(&g_sumr[threadIdx.x], s);
    }
}

__global__ void k_readv() {
    __shared__ float s_rv[256];
    s_rv[threadIdx.x] = 0.f;
    __syncthreads();
    const int w = threadIdx.x >> 5, lane = threadIdx.x & 31;
    const int wg = blockIdx.x * 8 + w;
    const float inv0 = 1.f / g_sumr[0], inv1 = 1.f / g_sumr[1];
    const float inv2 = 1.f / g_sumr[2], inv3 = 1.f / g_sumr[3];
    float acc[4][2];
#pragma unroll
    for (int r = 0; r < 4; r++) acc[r][0] = acc[r][1] = 0.f;
    for (int rr = 0; rr < 16; rr++) {
        int i = wg * 16 + rr;
        float m0 = g_M[(size_t)i * WD + lane], m1 = g_M[(size_t)i * WD + lane + 32];
        float invs[4] = {inv0, inv1, inv2, inv3};
#pragma unroll
        for (int r = 0; r < 4; r++) {
            float wr = g_rm[r] * g_Wbwd[i * 4 + r] + g_rm[4 + r] * g_er[i * 4 + r] * invs[r] +
                       g_rm[8 + r] * g_Wfwd[i * 4 + r];
            acc[r][0] += m0 * wr;
            acc[r][1] += m1 * wr;
        }
    }
#pragma unroll
    for (int r = 0; r < 4; r++) {
        atomicAdd(&s_rv[r * 64 + lane], acc[r][0]);
        atomicAdd(&s_rv[r * 64 + lane + 32], acc[r][1]);
    }
    __syncthreads();
    atomicAdd(&g_rv[threadIdx.x], s_rv[threadIdx.x]);
}

__global__ void k_final(const float* __restrict__ Wro, float* __restrict__ out) {
    __shared__ float s_rv[256];
    int j = threadIdx.x;
    s_rv[j] = g_rv[j];
    __syncthreads();
    float acc = g_outv[j];
#pragma unroll 8
    for (int k = 0; k < 256; k++) acc += s_rv[k] * Wro[k * 256 + j];
    out[j] = acc;
}

extern "C" void kernel_launch(void* const* d_in, const int* in_sizes, int n_in,
                              void* d_out, int out_size) {
    const float* x = (const float*)d_in[0];
    const float* dense_k = (const float*)d_in[1];
    const float* dense_b = (const float*)d_in[2];
    const float* lstm_k = (const float*)d_in[3];
    const float* lstm_r = (const float*)d_in[4];
    const float* lstm_b = (const float*)d_in[5];
    const float* W_output = (const float*)d_in[6];
    const float* W_interface = (const float*)d_in[7];
    const float* W_read_out = (const float*)d_in[8];
    const float* h = (const float*)d_in[9];
    const float* c = (const float*)d_in[10];
    const float* M = (const float*)d_in[11];
    const float* usage = (const float*)d_in[12];
    const float* L = (const float*)d_in[13];
    const float* W_prec = (const float*)d_in[14];
    const float* W_read = (const float*)d_in[15];
    const float* W_write = (const float*)d_in[16];
    const float* read_v = (const float*)d_in[17];
    float* out = (float*)d_out;

    cudaFuncSetAttribute(k_sort, cudaFuncAttributeMaxDynamicSharedMemorySize, 65536);

    k_prep<<<1, 1024>>>(x, dense_k, dense_b, h, c, read_v);
    for (int t = 0; t < 5; t++) {
        k_lstmA<<<dim3(12, KS), 256>>>(lstm_k, lstm_r, lstm_b, t);
        k_lstmB<<<3, 256>>>();
    }
    k_proj<<<dim3(3, KS2), 256>>>(W_output, W_interface);
    k_parse<<<1, 1024>>>();
    k_usage<<<32, 256>>>(usage, W_read, W_write);
    k_sort<<<1, 1024, 65536>>>();
    k_wscore<<<64, 256>>>(M);
    k_writeM<<<512, 256>>>(M);
    k_link<<<dim3(32, 8), 256>>>(L, W_prec, W_read);
    k_rscore<<<64, 256>>>();
    k_readv<<<64, 256>>>();
    k_final<<<1, 256>>>(W_read_out, out);
}

// round 3
// speedup vs baseline: 1.6691x; 1.6691x over previous
#include <cuda_runtime.h>
#include <math.h>

#define NN 8192
#define WD 64
#define OUTD 256
#define IFACED 471
#define CD 727
#define FCD 2908
#define J4 727          // FCD/4 float4 columns
#define LKS 64          // lstm split-K chunks
#define LCH 12          // rows per chunk (64*12 >= 727)
#define KS2 32
#define KCH2 23

__device__ __align__(16) float g_seq[5 * WD];
__device__ float g_h[CD], g_c[CD];
__device__ __align__(16) float g_z[FCD];
__device__ float g_oppart[KS2 * CD];
__device__ float g_outv[OUTD];
__device__ float g_kwn[WD];
__device__ float g_krn[4 * WD];
__device__ float g_bread[4], g_bwrite;
__device__ float g_erase[WD], g_writev[WD];
__device__ float g_free[4], g_ag, g_wg;
__device__ float g_rm[12];
__device__ float g_usage[NN];
__device__ int   g_rank[NN];
__device__ float g_Walloc[NN];
__device__ float g_ew[NN];
__device__ float g_sumw;
__device__ __align__(16) float g_Ww[NN];
__device__ __align__(16) float g_M[NN * WD];
__device__ __align__(16) float g_Wfwd[NN * 4];
__device__ __align__(16) float g_Wbwd[NN * 4];
__device__ __align__(16) float g_er[NN * 4];
__device__ float g_sumr[4];
__device__ float g_rv[OUTD];

__device__ __forceinline__ float sigm(float x) { return 1.f / (1.f + expf(-x)); }
__device__ __forceinline__ float sp(float x) { return x > 20.f ? x : log1pf(expf(x)); }

__global__ void k_prep(const float* __restrict__ x, const float* __restrict__ dk,
                       const float* __restrict__ db, const float* __restrict__ h,
                       const float* __restrict__ c, const float* __restrict__ read_v) {
    int t = threadIdx.x;
    if (t < WD) {
        float acc = db[t];
#pragma unroll 8
        for (int k = 0; k < 256; k++) acc += x[k] * dk[k * WD + t];
        g_seq[t] = acc;
    }
    if (t < 256) g_seq[WD + t] = read_v[t];
    if (t < CD) { g_h[t] = h[t]; g_c[t] = c[t]; }
    for (int i = t; i < FCD; i += 1024) g_z[i] = 0.f;
}

// z += xt[kc]*lstm_k[kc] + h[k0:k0+kn] @ lstm_r[k0:k0+kn]   (atomic accumulate)
__global__ void k_lstmA(const float* __restrict__ lstm_k, const float* __restrict__ lstm_r,
                        int t) {
    __shared__ float s_h[LCH];
    const int j4 = blockIdx.x * 128 + threadIdx.x;
    const int kc = blockIdx.y;
    const int k0 = kc * LCH;
    const int kn = max(0, min(LCH, CD - k0));
    if (threadIdx.x < kn) s_h[threadIdx.x] = g_h[k0 + threadIdx.x];
    __syncthreads();
    if (j4 >= J4) return;
    const float4* lr = (const float4*)lstm_r;
    const float4* lk = (const float4*)lstm_k;
    float xs = g_seq[t * WD + kc];
    float4 kv = lk[kc * J4 + j4];
    float ax = xs * kv.x, ay = xs * kv.y, az = xs * kv.z, aw = xs * kv.w;
#pragma unroll
    for (int k = 0; k < LCH; k++) {
        if (k >= kn) break;
        float hv = s_h[k];
        float4 rv = lr[(size_t)(k0 + k) * J4 + j4];
        ax += hv * rv.x; ay += hv * rv.y; az += hv * rv.z; aw += hv * rv.w;
    }
    atomicAdd(&g_z[j4 * 4 + 0], ax);
    atomicAdd(&g_z[j4 * 4 + 1], ay);
    atomicAdd(&g_z[j4 * 4 + 2], az);
    atomicAdd(&g_z[j4 * 4 + 3], aw);
}

__global__ void k_gate(const float* __restrict__ lstm_b) {
    const int j = threadIdx.x;
    float cn = 0.f, hn = 0.f;
    float zi = 0.f, zf = 0.f, zg = 0.f, zo = 0.f;
    if (j < CD) {
        zi = g_z[j] + lstm_b[j];
        zf = g_z[CD + j] + lstm_b[CD + j];
        zg = g_z[2 * CD + j] + lstm_b[2 * CD + j];
        zo = g_z[3 * CD + j] + lstm_b[3 * CD + j];
    }
    __syncthreads();
    for (int i = threadIdx.x; i < FCD; i += 1024) g_z[i] = 0.f;
    if (j < CD) {
        cn = sigm(zf) * g_c[j] + sigm(zi) * tanhf(zg);
        hn = sigm(zo) * tanhf(cn);
        g_c[j] = cn;
        g_h[j] = hn;
    }
}

__global__ void k_proj(const float* __restrict__ Wout, const float* __restrict__ Wif) {
    __shared__ float sh[KCH2];
    const int j = blockIdx.x * 256 + threadIdx.x;
    const int kc = blockIdx.y;
    const int k0 = kc * KCH2;
    const int kn = max(0, min(KCH2, CD - k0));
    if (threadIdx.x < kn) sh[threadIdx.x] = g_h[k0 + threadIdx.x];
    __syncthreads();
    if (j >= CD) return;
    float acc = 0.f;
    if (j < 256) {
#pragma unroll
        for (int k = 0; k < KCH2; k++) {
            if (k >= kn) break;
            acc += sh[k] * Wout[(size_t)(k0 + k) * 256 + j];
        }
    } else {
        int jj = j - 256;
#pragma unroll
        for (int k = 0; k < KCH2; k++) {
            if (k >= kn) break;
            acc += sh[k] * Wif[(size_t)(k0 + k) * IFACED + jj];
        }
    }
    g_oppart[kc * CD + j] = acc;
}

__global__ void k_parse() {
    __shared__ float sif[IFACED];
    const int t = threadIdx.x;
    if (t < CD) {
        float v = 0.f;
#pragma unroll
        for (int p = 0; p < KS2; p++) v += g_oppart[p * CD + t];
        if (t < 256) g_outv[t] = v; else sif[t - 256] = v;
    }
    __syncthreads();
    const int w = t >> 5, lane = t & 31;
    if (w == 0) {
        float s = 0.f;
        for (int e = lane; e < 64; e += 32) { float v = sif[260 + e]; s += v * v; }
        for (int o = 16; o; o >>= 1) s += __shfl_xor_sync(0xffffffffu, s, o);
        float inv = rsqrtf(fmaxf(s, 1e-12f));
        for (int e = lane; e < 64; e += 32) g_kwn[e] = sif[260 + e] * inv;
    } else if (w <= 4) {
        int r = w - 1;
        float s = 0.f;
        for (int e = lane; e < 64; e += 32) { float v = sif[r * 64 + e]; s += v * v; }
        for (int o = 16; o; o >>= 1) s += __shfl_xor_sync(0xffffffffu, s, o);
        float inv = rsqrtf(fmaxf(s, 1e-12f));
        for (int e = lane; e < 64; e += 32) g_krn[r * 64 + e] = sif[r * 64 + e] * inv;
    } else if (w == 5) {
        if (lane < 4) g_bread[lane] = 1.f + sp(sif[256 + lane]);
        if (lane == 4) g_bwrite = 1.f + sp(sif[324]);
        if (lane >= 8 && lane < 12) g_free[lane - 8] = sigm(sif[453 + lane - 8]);
        if (lane == 12) g_ag = sigm(sif[457]);
        if (lane == 13) g_wg = sigm(sif[458]);
        if (lane >= 16 && lane < 20) {
            int r = lane - 16;
            float e0 = expf(sif[459 + r]);
            float e1 = expf(sif[463 + r]);
            float e2 = expf(sif[467 + r]);
            float si = 1.f / (e0 + e1 + e2);
            g_rm[r] = e0 * si; g_rm[4 + r] = e1 * si; g_rm[8 + r] = e2 * si;
        }
    } else if (w == 6) {
        for (int e = lane; e < 64; e += 32) {
            g_erase[e] = sigm(sif[325 + e]);
            g_writev[e] = sif[389 + e];
        }
    }
}

__global__ void k_usage(const float* __restrict__ usage_in, const float* __restrict__ Wread_in,
                        const float* __restrict__ Wwrite_in) {
    const int i = blockIdx.x * 256 + threadIdx.x;
    if (i >= NN) return;
    float ret = 1.f;
#pragma unroll
    for (int r = 0; r < 4; r++) ret *= (1.f - g_free[r] * Wread_in[i * 4 + r]);
    float u = usage_in[i], ww = Wwrite_in[i];
    g_usage[i] = (u + ww - u * ww) * ret;
    g_rank[i] = 0;
    float4 z = make_float4(0.f, 0.f, 0.f, 0.f);
    ((float4*)g_Wfwd)[i] = z;
    ((float4*)g_Wbwd)[i] = z;
    if (i < OUTD) g_rv[i] = 0.f;
    if (i == 0) g_sumw = 0.f;
    if (i < 4) g_sumr[i] = 0.f;
}

// brute-force stable rank: rank_i = #{j : key_j < key_i}, key = (usage_bits<<13)|idx
__global__ void k_rank() {
    __shared__ unsigned long long s_k[256];
    const int bi = blockIdx.x, bj = blockIdx.y;
    {
        int jg = bj * 256 + threadIdx.x;
        s_k[threadIdx.x] = ((unsigned long long)__float_as_uint(g_usage[jg]) << 13) | (unsigned)jg;
    }
    __syncthreads();
    const int i0 = bi * 1024 + threadIdx.x * 4;
    unsigned long long ki0 = ((unsigned long long)__float_as_uint(g_usage[i0 + 0]) << 13) | (unsigned)(i0 + 0);
    unsigned long long ki1 = ((unsigned long long)__float_as_uint(g_usage[i0 + 1]) << 13) | (unsigned)(i0 + 1);
    unsigned long long ki2 = ((unsigned long long)__float_as_uint(g_usage[i0 + 2]) << 13) | (unsigned)(i0 + 2);
    unsigned long long ki3 = ((unsigned long long)__float_as_uint(g_usage[i0 + 3]) << 13) | (unsigned)(i0 + 3);
    int c0 = 0, c1 = 0, c2 = 0, c3 = 0;
#pragma unroll 8
    for (int jj = 0; jj < 256; jj++) {
        unsigned long long kj = s_k[jj];
        c0 += (kj < ki0); c1 += (kj < ki1); c2 += (kj < ki2); c3 += (kj < ki3);
    }
    atomicAdd(&g_rank[i0 + 0], c0);
    atomicAdd(&g_rank[i0 + 1], c1);
    atomicAdd(&g_rank[i0 + 2], c2);
    atomicAdd(&g_rank[i0 + 3], c3);
}

// scatter by rank -> exclusive cumprod -> W_alloc  (single block)
__global__ void k_alloc() {
    __shared__ float s_s[NN];
    __shared__ float wtot[32];
    const int t = threadIdx.x;
    for (int i = t; i < NN; i += 1024) s_s[g_rank[i]] = g_usage[i];
    __syncthreads();
    float loc[8], p = 1.f;
#pragma unroll
    for (int m = 0; m < 8; m++) { loc[m] = p; p *= s_s[t * 8 + m]; }
    const int lane = t & 31, w = t >> 5;
    float sc = p;
    for (int o = 1; o < 32; o <<= 1) {
        float v = __shfl_up_sync(0xffffffffu, sc, o);
        if (lane >= o) sc *= v;
    }
    if (lane == 31) wtot[w] = sc;
    __syncthreads();
    if (w == 0) {
        float s2 = wtot[lane];
        for (int o = 1; o < 32; o <<= 1) {
            float z = __shfl_up_sync(0xffffffffu, s2, o);
            if (lane >= o) s2 *= z;
        }
        wtot[lane] = s2;
    }
    __syncthreads();
    float excl = __shfl_up_sync(0xffffffffu, sc, 1);
    if (lane == 0) excl = 1.f;
    float pref = (w > 0 ? wtot[w - 1] : 1.f) * excl;
#pragma unroll
    for (int m = 0; m < 8; m++) s_s[t * 8 + m] = pref * loc[m];
    __syncthreads();
    for (int i = t; i < NN; i += 1024) {
        float u = g_usage[i];
        g_Walloc[i] = (1.f - u) * s_s[g_rank[i]];
    }
}

__global__ void k_wscore(const float* __restrict__ M) {
    __shared__ float bsum[8];
    const int w = threadIdx.x >> 5, lane = threadIdx.x & 31;
    const int wg = blockIdx.x * 8 + w;
    const float ka = g_kwn[lane], kb = g_kwn[lane + 32];
    const float bw = g_bwrite;
    float local = 0.f;
    for (int rr = 0; rr < 16; rr++) {
        int i = wg * 16 + rr;
        const float* row = M + (size_t)i * WD;
        float a0 = row[lane], a1 = row[lane + 32];
        float ss = a0 * a0 + a1 * a1;
        float d = a0 * ka + a1 * kb;
        for (int o = 16; o; o >>= 1) {
            ss += __shfl_xor_sync(0xffffffffu, ss, o);
            d += __shfl_xor_sync(0xffffffffu, d, o);
        }
        if (lane == 0) {
            float e = expf(bw * d * rsqrtf(fmaxf(ss, 1e-12f)));
            g_ew[i] = e;
            local += e;
        }
    }
    if (lane == 0) bsum[w] = local;
    __syncthreads();
    if (threadIdx.x == 0) {
        float s = 0.f;
        for (int k = 0; k < 8; k++) s += bsum[k];
        atomicAdd(&g_sumw, s);
    }
}

__global__ void k_writeM(const float* __restrict__ M) {
    const float inv_s = 1.f / g_sumw;
    const float wgt = g_wg, ag = g_ag, iag = 1.f - g_ag;
    for (int e = blockIdx.x * blockDim.x + threadIdx.x; e < NN * WD; e += gridDim.x * blockDim.x) {
        int i = e >> 6, wc = e & 63;
        float ww = wgt * (ag * g_Walloc[i] + iag * g_ew[i] * inv_s);
        g_M[e] = M[e] * (1.f - ww * g_erase[wc]) + ww * g_writev[wc];
        if (wc == 0) g_Ww[i] = ww;
    }
}

// fused: W_fwd = L_new @ Wr, W_bwd = L_new^T @ Wr, L_new formed on the fly (never stored)
__global__ void __launch_bounds__(256, 2) k_link(const float* __restrict__ L,
                                                 const float* __restrict__ Wprec,
                                                 const float* __restrict__ Wread) {
    __shared__ float s_ww[512];
    __shared__ float s_wr[512 * 4];
    __shared__ float s_red[8][1024];
    const int jb = blockIdx.x, ib = blockIdx.y;
    const int i0 = ib * 512;
    for (int k = threadIdx.x; k < 512; k += 256) {
        s_ww[k] = g_Ww[i0 + k];
        float4 v = ((const float4*)Wread)[i0 + k];
        s_wr[k * 4] = v.x; s_wr[k * 4 + 1] = v.y; s_wr[k * 4 + 2] = v.z; s_wr[k * 4 + 3] = v.w;
    }
    __syncthreads();
    const int w = threadIdx.x >> 5, lane = threadIdx.x & 31;
    const int j0 = jb * 256 + lane * 4;
    float tj[2][4], wpj[2][4], wrj[2][4][4], bwd[2][4][4];
#pragma unroll
    for (int cc = 0; cc < 2; cc++) {
        int jj = j0 + cc * 128;
        float4 a = *(const float4*)(g_Ww + jj);
        tj[cc][0] = 1.f - a.x; tj[cc][1] = 1.f - a.y; tj[cc][2] = 1.f - a.z; tj[cc][3] = 1.f - a.w;
        float4 b = *(const float4*)(Wprec + jj);
        wpj[cc][0] = b.x; wpj[cc][1] = b.y; wpj[cc][2] = b.z; wpj[cc][3] = b.w;
#pragma unroll
        for (int k2 = 0; k2 < 4; k2++) {
            float4 v = ((const float4*)Wread)[jj + k2];
            wrj[cc][k2][0] = v.x; wrj[cc][k2][1] = v.y; wrj[cc][k2][2] = v.z; wrj[cc][k2][3] = v.w;
            bwd[cc][k2][0] = bwd[cc][k2][1] = bwd[cc][k2][2] = bwd[cc][k2][3] = 0.f;
        }
    }
    for (int il = w; il < 512; il += 16) {
        const int ia = i0 + il, ib2 = ia + 8;
        const float4* LrA = (const float4*)(L + (size_t)ia * NN);
        const float4* LrB = (const float4*)(L + (size_t)ib2 * NN);
        float4 lvA0 = __ldcs(LrA + (j0 >> 2));
        float4 lvA1 = __ldcs(LrA + (j0 >> 2) + 32);
        float4 lvB0 = __ldcs(LrB + (j0 >> 2));
        float4 lvB1 = __ldcs(LrB + (j0 >> 2) + 32);
        float fa0 = 0.f, fa1 = 0.f, fa2 = 0.f, fa3 = 0.f;
        float fb0 = 0.f, fb1 = 0.f, fb2 = 0.f, fb3 = 0.f;
        const float wwA = s_ww[il], wwB = s_ww[il + 8];
        const float wriA0 = s_wr[il * 4], wriA1 = s_wr[il * 4 + 1];
        const float wriA2 = s_wr[il * 4 + 2], wriA3 = s_wr[il * 4 + 3];
        const float wriB0 = s_wr[(il + 8) * 4], wriB1 = s_wr[(il + 8) * 4 + 1];
        const float wriB2 = s_wr[(il + 8) * 4 + 2], wriB3 = s_wr[(il + 8) * 4 + 3];
#pragma unroll
        for (int cc = 0; cc < 2; cc++) {
            float leA[4], leB[4];
            if (cc == 0) { leA[0]=lvA0.x; leA[1]=lvA0.y; leA[2]=lvA0.z; leA[3]=lvA0.w;
                           leB[0]=lvB0.x; leB[1]=lvB0.y; leB[2]=lvB0.z; leB[3]=lvB0.w; }
            else         { leA[0]=lvA1.x; leA[1]=lvA1.y; leA[2]=lvA1.z; leA[3]=lvA1.w;
                           leB[0]=lvB1.x; leB[1]=lvB1.y; leB[2]=lvB1.z; leB[3]=lvB1.w; }
#pragma unroll
            for (int k2 = 0; k2 < 4; k2++) {
                int jg = j0 + cc * 128 + k2;
                float nlA = (tj[cc][k2] - wwA) * leA[k2] + wwA * wpj[cc][k2];
                float nlB = (tj[cc][k2] - wwB) * leB[k2] + wwB * wpj[cc][k2];
                if (jg == ia) nlA = 0.f;
                if (jg == ib2) nlB = 0.f;
                fa0 += nlA * wrj[cc][k2][0]; fa1 += nlA * wrj[cc][k2][1];
                fa2 += nlA * wrj[cc][k2][2]; fa3 += nlA * wrj[cc][k2][3];
                fb0 += nlB * wrj[cc][k2][0]; fb1 += nlB * wrj[cc][k2][1];
                fb2 += nlB * wrj[cc][k2][2]; fb3 += nlB * wrj[cc][k2][3];
                bwd[cc][k2][0] += nlA * wriA0 + nlB * wriB0;
                bwd[cc][k2][1] += nlA * wriA1 + nlB * wriB1;
                bwd[cc][k2][2] += nlA * wriA2 + nlB * wriB2;
                bwd[cc][k2][3] += nlA * wriA3 + nlB * wriB3;
            }
        }
#pragma unroll
        for (int o = 16; o; o >>= 1) {
            fa0 += __shfl_xor_sync(0xffffffffu, fa0, o);
            fa1 += __shfl_xor_sync(0xffffffffu, fa1, o);
            fa2 += __shfl_xor_sync(0xffffffffu, fa2, o);
            fa3 += __shfl_xor_sync(0xffffffffu, fa3, o);
            fb0 += __shfl_xor_sync(0xffffffffu, fb0, o);
            fb1 += __shfl_xor_sync(0xffffffffu, fb1, o);
            fb2 += __shfl_xor_sync(0xffffffffu, fb2, o);
            fb3 += __shfl_xor_sync(0xffffffffu, fb3, o);
        }
        if (lane < 4) {
            float fv = lane == 0 ? fa0 : lane == 1 ? fa1 : lane == 2 ? fa2 : fa3;
            atomicAdd(&g_Wfwd[ia * 4 + lane], fv);
            float gv = lane == 0 ? fb0 : lane == 1 ? fb1 : lane == 2 ? fb2 : fb3;
            atomicAdd(&g_Wfwd[ib2 * 4 + lane], gv);
        }
    }
    // cross-warp reduce bwd, then one atomic per (j,r)
#pragma unroll
    for (int cc = 0; cc < 2; cc++)
#pragma unroll
        for (int k2 = 0; k2 < 4; k2++)
#pragma unroll
            for (int r = 0; r < 4; r++)
                s_red[w][(cc * 128 + lane * 4 + k2) * 4 + r] = bwd[cc][k2][r];
    __syncthreads();
#pragma unroll
    for (int q = 0; q < 4; q++) {
        int pos = q * 256 + threadIdx.x;
        float v = 0.f;
#pragma unroll
        for (int ww2 = 0; ww2 < 8; ww2++) v += s_red[ww2][pos];
        atomicAdd(&g_Wbwd[jb * 1024 + pos], v);
    }
}

__global__ void k_rscore() {
    __shared__ float bs[8][4];
    const int w = threadIdx.x >> 5, lane = threadIdx.x & 31;
    const int wg = blockIdx.x * 8 + w;
    const float k0a = g_krn[lane], k0b = g_krn[lane + 32];
    const float k1a = g_krn[64 + lane], k1b = g_krn[96 + lane];
    const float k2a = g_krn[128 + lane], k2b = g_krn[160 + lane];
    const float k3a = g_krn[192 + lane], k3b = g_krn[224 + lane];
    const float br0 = g_bread[0], br1 = g_bread[1], br2 = g_bread[2], br3 = g_bread[3];
    float l0 = 0.f, l1 = 0.f, l2 = 0.f, l3 = 0.f;
    for (int rr = 0; rr < 16; rr++) {
        int i = wg * 16 + rr;
        const float* row = g_M + (size_t)i * WD;
        float a0 = row[lane], a1 = row[lane + 32];
        float ss = a0 * a0 + a1 * a1;
        float d0 = a0 * k0a + a1 * k0b;
        float d1 = a0 * k1a + a1 * k1b;
        float d2 = a0 * k2a + a1 * k2b;
        float d3 = a0 * k3a + a1 * k3b;
        for (int o = 16; o; o >>= 1) {
            ss += __shfl_xor_sync(0xffffffffu, ss, o);
            d0 += __shfl_xor_sync(0xffffffffu, d0, o);
            d1 += __shfl_xor_sync(0xffffffffu, d1, o);
            d2 += __shfl_xor_sync(0xffffffffu, d2, o);
            d3 += __shfl_xor_sync(0xffffffffu, d3, o);
        }
        if (lane == 0) {
            float inv = rsqrtf(fmaxf(ss, 1e-12f));
            float e0 = expf(br0 * d0 * inv), e1 = expf(br1 * d1 * inv);
            float e2 = expf(br2 * d2 * inv), e3 = expf(br3 * d3 * inv);
            g_er[i * 4] = e0; g_er[i * 4 + 1] = e1; g_er[i * 4 + 2] = e2; g_er[i * 4 + 3] = e3;
            l0 += e0; l1 += e1; l2 += e2; l3 += e3;
        }
    }
    if (lane == 0) { bs[w][0] = l0; bs[w][1] = l1; bs[w][2] = l2; bs[w][3] = l3; }
    __syncthreads();
    if (threadIdx.x < 4) {
        float s = 0.f;
        for (int k = 0; k < 8; k++) s += bs[k][threadIdx.x];
        atomicAdd(&g_sumr[threadIdx.x], s);
    }
}

__global__ void k_readv() {
    __shared__ float s_rv[256];
    s_rv[threadIdx.x] = 0.f;
    __syncthreads();
    const int w = threadIdx.x >> 5, lane = threadIdx.x & 31;
    const int wg = blockIdx.x * 8 + w;
    const float inv0 = 1.f / g_sumr[0], inv1 = 1.f / g_sumr[1];
    const float inv2 = 1.f / g_sumr[2], inv3 = 1.f / g_sumr[3];
    float acc[4][2];
#pragma unroll
    for (int r = 0; r < 4; r++) acc[r][0] = acc[r][1] = 0.f;
    for (int rr = 0; rr < 16; rr++) {
        int i = wg * 16 + rr;
        float m0 = g_M[(size_t)i * WD + lane], m1 = g_M[(size_t)i * WD + lane + 32];
        float invs[4] = {inv0, inv1, inv2, inv3};
#pragma unroll
        for (int r = 0; r < 4; r++) {
            float wr = g_rm[r] * g_Wbwd[i * 4 + r] + g_rm[4 + r] * g_er[i * 4 + r] * invs[r] +
                       g_rm[8 + r] * g_Wfwd[i * 4 + r];
            acc[r][0] += m0 * wr;
            acc[r][1] += m1 * wr;
        }
    }
#pragma unroll
    for (int r = 0; r < 4; r++) {
        atomicAdd(&s_rv[r * 64 + lane], acc[r][0]);
        atomicAdd(&s_rv[r * 64 + lane + 32], acc[r][1]);
    }
    __syncthreads();
    atomicAdd(&g_rv[threadIdx.x], s_rv[threadIdx.x]);
}

__global__ void k_final(const float* __restrict__ Wro, float* __restrict__ out) {
    __shared__ float s_rv[256];
    int j = threadIdx.x;
    s_rv[j] = g_rv[j];
    __syncthreads();
    float acc = g_outv[j];
#pragma unroll 8
    for (int k = 0; k < 256; k++) acc += s_rv[k] * Wro[k * 256 + j];
    out[j] = acc;
}

extern "C" void kernel_launch(void* const* d_in, const int* in_sizes, int n_in,
                              void* d_out, int out_size) {
    const float* x = (const float*)d_in[0];
    const float* dense_k = (const float*)d_in[1];
    const float* dense_b = (const float*)d_in[2];
    const float* lstm_k = (const float*)d_in[3];
    const float* lstm_r = (const float*)d_in[4];
    const float* lstm_b = (const float*)d_in[5];
    const float* W_output = (const float*)d_in[6];
    const float* W_interface = (const float*)d_in[7];
    const float* W_read_out = (const float*)d_in[8];
    const float* h = (const float*)d_in[9];
    const float* c = (const float*)d_in[10];
    const float* M = (const float*)d_in[11];
    const float* usage = (const float*)d_in[12];
    const float* L = (const float*)d_in[13];
    const float* W_prec = (const float*)d_in[14];
    const float* W_read = (const float*)d_in[15];
    const float* W_write = (const float*)d_in[16];
    const float* read_v = (const float*)d_in[17];
    float* out = (float*)d_out;

    k_prep<<<1, 1024>>>(x, dense_k, dense_b, h, c, read_v);
    for (int t = 0; t < 5; t++) {
        k_lstmA<<<dim3(6, LKS), 128>>>(lstm_k, lstm_r, t);
        k_gate<<<1, 1024>>>(lstm_b);
    }
    k_proj<<<dim3(3, KS2), 256>>>(W_output, W_interface);
    k_parse<<<1, 1024>>>();
    k_usage<<<32, 256>>>(usage, W_read, W_write);
    k_rank<<<dim3(8, 32), 256>>>();
    k_alloc<<<1, 1024>>>();
    k_wscore<<<64, 256>>>(M);
    k_writeM<<<512, 256>>>(M);
    k_link<<<dim3(32, 16), 256>>>(L, W_prec, W_read);
    k_rscore<<<64, 256>>>();
    k_readv<<<64, 256>>>();
    k_final<<<1, 256>>>(W_read_out, out);
}